// round 4
// baseline (speedup 1.0000x reference)
#include <cuda_runtime.h>
#include <stdint.h>

#define D 128
#define MAX_N (1 << 18)        // >= 100000 segments
#define MAX_E (1 << 21)        // >= 2000000 edges
#define GATHER_BATCH 8

__device__ int g_counts[MAX_N];
__device__ int g_offsets[MAX_N + 1];
__device__ int g_cursor[MAX_N];
__device__ int g_perm[MAX_E];

// ---------------------------------------------------------------------------
// K0: zero counts
// ---------------------------------------------------------------------------
__global__ void zero_counts_kernel(int N) {
    int i = blockIdx.x * blockDim.x + threadIdx.x;
    if (i < N) g_counts[i] = 0;
}

// ---------------------------------------------------------------------------
// K1: histogram of segment ids
// ---------------------------------------------------------------------------
__global__ void hist_kernel(const int* __restrict__ index, int E) {
    int i = blockIdx.x * blockDim.x + threadIdx.x;
    if (i < E) atomicAdd(&g_counts[__ldg(&index[i])], 1);
}

// ---------------------------------------------------------------------------
// K2: exclusive scan of counts -> offsets (+ cursor copy). Single block.
// ---------------------------------------------------------------------------
__global__ __launch_bounds__(1024) void scan_kernel(int N) {
    __shared__ int s[1024];
    int t = threadIdx.x;
    int chunk = (N + 1023) / 1024;
    int beg = t * chunk;
    int end = min(beg + chunk, N);

    int sum = 0;
    for (int i = beg; i < end; i++) sum += g_counts[i];
    s[t] = sum;
    __syncthreads();

    // Hillis-Steele inclusive scan over 1024 partials
    for (int d = 1; d < 1024; d <<= 1) {
        int v = (t >= d) ? s[t - d] : 0;
        __syncthreads();
        s[t] += v;
        __syncthreads();
    }
    int run = (t == 0) ? 0 : s[t - 1];   // exclusive prefix for this chunk

    for (int i = beg; i < end; i++) {
        g_offsets[i] = run;
        g_cursor[i] = run;
        run += g_counts[i];
    }
    if (t == 1023) g_offsets[N] = s[1023];
}

// ---------------------------------------------------------------------------
// K3: scatter edge ids into segment-sorted permutation
// ---------------------------------------------------------------------------
__global__ void scatter_kernel(const int* __restrict__ index, int E) {
    int i = blockIdx.x * blockDim.x + threadIdx.x;
    if (i >= E) return;
    int seg = __ldg(&index[i]);
    int pos = atomicAdd(&g_cursor[seg], 1);
    g_perm[pos] = i;
}

// ---------------------------------------------------------------------------
// K4: gather + reduce + scale. One warp per segment.
// ---------------------------------------------------------------------------
__global__ __launch_bounds__(256) void gather_kernel(
        const float4* __restrict__ msg4,
        float4* __restrict__ out4,
        int N) {
    int warp_id = (blockIdx.x * blockDim.x + threadIdx.x) >> 5;
    int lane = threadIdx.x & 31;
    if (warp_id >= N) return;

    int beg = g_offsets[warp_id];
    int end = g_offsets[warp_id + 1];
    int cnt = end - beg;

    float4 acc = make_float4(0.f, 0.f, 0.f, 0.f);
    int i = beg;
    while (i < end) {
        int nb = min(end - i, GATHER_BATCH);
        int e = (lane < nb) ? g_perm[i + lane] : 0;
#pragma unroll
        for (int j = 0; j < GATHER_BATCH; j++) {
            if (j >= nb) break;
            int ej = __shfl_sync(0xffffffffu, e, j);
            float4 v = __ldg(&msg4[(long long)ej * (D / 4) + lane]);
            acc.x += v.x; acc.y += v.y; acc.z += v.z; acc.w += v.w;
        }
        i += nb;
    }

    float inv = 1.0f / fmaxf((float)cnt, 1.0f);
    acc.x *= inv; acc.y *= inv; acc.z *= inv; acc.w *= inv;
    out4[(long long)warp_id * (D / 4) + lane] = acc;   // empty segments -> 0
}

// ---------------------------------------------------------------------------
extern "C" void kernel_launch(void* const* d_in, const int* in_sizes, int n_in,
                              void* d_out, int out_size) {
    const float4* msg4  = (const float4*)d_in[0];
    const int*    index = (const int*)d_in[1];
    // d_in[2] (t) unused by the reference
    float4* out4 = (float4*)d_out;

    int E = in_sizes[1];
    int N = out_size / D;

    zero_counts_kernel<<<(N + 255) / 256, 256>>>(N);
    hist_kernel<<<(E + 255) / 256, 256>>>(index, E);
    scan_kernel<<<1, 1024>>>(N);
    scatter_kernel<<<(E + 255) / 256, 256>>>(index, E);
    {
        long long total_threads = (long long)N * 32;
        int blocks = (int)((total_threads + 255) / 256);
        gather_kernel<<<blocks, 256>>>(msg4, out4, N);
    }
}

// round 5
// speedup vs baseline: 1.0489x; 1.0489x over previous
#include <cuda_runtime.h>
#include <stdint.h>

#define D 128
#define MAX_N (1 << 18)        // >= 100000 segments
#define EB 8                   // edges per SMEM buffer (per warp)
#define WPB 4                  // warps per block
#define EPW 32                 // edges per warp (EB * 4 batches)

__device__ int g_counts[MAX_N];

// ---------------------------------------------------------------------------
// K0: zero output + counts
// ---------------------------------------------------------------------------
__global__ void zero_kernel(float4* __restrict__ out4, long long n4, int N) {
    long long i = (long long)blockIdx.x * blockDim.x + threadIdx.x;
    long long stride = (long long)gridDim.x * blockDim.x;
    for (long long k = i; k < n4; k += stride)
        out4[k] = make_float4(0.f, 0.f, 0.f, 0.f);
    for (long long k = i; k < N; k += stride)
        g_counts[k] = 0;
}

// ---------------------------------------------------------------------------
// K1: histogram of segment ids (2M scalar atomics, cheap)
// ---------------------------------------------------------------------------
__global__ void hist_kernel(const int* __restrict__ index, int E) {
    int i = blockIdx.x * blockDim.x + threadIdx.x;
    if (i < E) atomicAdd(&g_counts[__ldg(&index[i])], 1);
}

// ---------------------------------------------------------------------------
// K2: scatter-add via TMA bulk reduce. One warp handles EPW edges:
//     stage 8 rows in SMEM, issue 8x cp.reduce.async.bulk (512B each),
//     double-buffered with per-thread bulk groups.
// ---------------------------------------------------------------------------
__global__ __launch_bounds__(WPB * 32) void edge_tma_kernel(
        const float4* __restrict__ msg4,
        const int* __restrict__ index,
        float* __restrict__ out,
        int E) {
    __shared__ float4 sbuf[WPB][2][EB][D / 4];   // 4 * 2 * 8 * 512B = 32 KB

    int warp = threadIdx.x >> 5;
    int lane = threadIdx.x & 31;
    long long base = ((long long)blockIdx.x * WPB + warp) * EPW;
    if (base >= E) return;

    int cur = 0;
#pragma unroll
    for (int b = 0; b < EPW / EB; b++) {
        long long ebase = base + (long long)b * EB;
        if (ebase >= E) break;
        int nb = (int)min((long long)EB, E - ebase);

        // segment id for this lane's edge (lanes 0..nb-1 each own one edge)
        int seg = (lane < nb) ? __ldg(&index[ebase + lane]) : 0;

        // stage rows: warp-coalesced LDG.128 -> STS.128
#pragma unroll
        for (int e = 0; e < EB; e++) {
            if (e >= nb) break;
            float4 v = __ldg(&msg4[(ebase + e) * (D / 4) + lane]);
            sbuf[warp][cur][e][lane] = v;
        }
        __syncwarp();

        // publish generic-proxy SMEM writes to the async proxy, then each
        // owning lane issues one 512B bulk-reduce into its segment's row
        if (lane < nb) {
            asm volatile("fence.proxy.async.shared::cta;" ::: "memory");
            uint32_t src = (uint32_t)__cvta_generic_to_shared(
                               &sbuf[warp][cur][lane][0]);
            float* dst = out + (long long)seg * D;
            asm volatile(
                "cp.reduce.async.bulk.global.shared::cta.bulk_group.add.f32 "
                "[%0], [%1], %2;"
                :: "l"(dst), "r"(src), "n"(D * 4) : "memory");
            asm volatile("cp.async.bulk.commit_group;" ::: "memory");
        }

        cur ^= 1;
        // before overwriting the other buffer, drain all but the newest group
        if (lane < EB)
            asm volatile("cp.async.bulk.wait_group 1;" ::: "memory");
        __syncwarp();
    }
    // drain remaining groups before SMEM is reused by the next CTA
    if (lane < EB)
        asm volatile("cp.async.bulk.wait_group 0;" ::: "memory");
}

// ---------------------------------------------------------------------------
// K3: divide sums by max(count, 1)
// ---------------------------------------------------------------------------
__global__ void divide_kernel(float4* __restrict__ out4, int N) {
    long long i = (long long)blockIdx.x * blockDim.x + threadIdx.x;
    long long total = (long long)N * (D / 4);
    if (i >= total) return;
    int row = (int)(i >> 5);           // D/4 == 32
    float c = (float)g_counts[row];
    float inv = 1.0f / fmaxf(c, 1.0f);
    float4 v = out4[i];
    v.x *= inv; v.y *= inv; v.z *= inv; v.w *= inv;
    out4[i] = v;
}

// ---------------------------------------------------------------------------
extern "C" void kernel_launch(void* const* d_in, const int* in_sizes, int n_in,
                              void* d_out, int out_size) {
    const float4* msg4  = (const float4*)d_in[0];
    const int*    index = (const int*)d_in[1];
    // d_in[2] (t) unused by the reference
    float* out = (float*)d_out;

    int E = in_sizes[1];
    int N = out_size / D;
    long long n4 = (long long)out_size / 4;

    zero_kernel<<<2048, 256>>>((float4*)out, n4, N);
    hist_kernel<<<(E + 255) / 256, 256>>>(index, E);
    {
        long long warps = ((long long)E + EPW - 1) / EPW;
        int blocks = (int)((warps + WPB - 1) / WPB);
        edge_tma_kernel<<<blocks, WPB * 32>>>(msg4, index, out, E);
    }
    {
        long long total = (long long)N * (D / 4);
        int blocks = (int)((total + 255) / 256);
        divide_kernel<<<blocks, 256>>>((float4*)out, N);
    }
}

// round 6
// speedup vs baseline: 1.3966x; 1.3315x over previous
#include <cuda_runtime.h>
#include <stdint.h>

#define D 128
#define MAX_N (1 << 18)     // >= 100000 segments
#define EPB 256             // edges per block (both types)
#define TEB 4               // TMA slots per buffer per warp

__device__ int g_counts[MAX_N];

// ---------------------------------------------------------------------------
// K0: zero output + counts
// ---------------------------------------------------------------------------
__global__ void zero_kernel(float4* __restrict__ out4, long long n4, int N) {
    long long i = (long long)blockIdx.x * blockDim.x + threadIdx.x;
    long long stride = (long long)gridDim.x * blockDim.x;
    for (long long k = i; k < n4; k += stride)
        out4[k] = make_float4(0.f, 0.f, 0.f, 0.f);
    for (long long k = i; k < N; k += stride)
        g_counts[k] = 0;
}

// ---------------------------------------------------------------------------
// K1: hybrid scatter-add. Blocks interleaved 4 REDG : 3 TMA per group of 7,
//     so every wave saturates BOTH the LSU red pipe and the TMA engine.
//     Each block covers EPB=256 edges (8 warps x 32 edges).
// ---------------------------------------------------------------------------
__global__ __launch_bounds__(256) void hybrid_kernel(
        const float4* __restrict__ msg4,
        const int* __restrict__ index,
        float* __restrict__ out,
        long long E_red, long long E) {
    __shared__ float4 sbuf[8][2][TEB][D / 4];   // 8 warps * 2 buf * 4 rows * 512B = 32KB

    int warp = threadIdx.x >> 5;
    int lane = threadIdx.x & 31;

    int g = blockIdx.x / 7;
    int r = blockIdx.x % 7;

    if (r < 4) {
        // ---------------- REDG path: edges [0, E_red) ----------------
        long long blk = (long long)g * 4 + r;
        long long wbase = blk * EPB + (long long)warp * 32;
        if (wbase >= E_red) return;

#pragma unroll
        for (int b = 0; b < 8; b++) {
            long long e0 = wbase + b * 4;
            if (e0 >= E_red) break;
            int nb = (int)min(4LL, E_red - e0);

            int seg_l = (lane < nb) ? __ldg(&index[e0 + lane]) : 0;

            float4 v[4];
#pragma unroll
            for (int e = 0; e < 4; e++)
                if (e < nb) v[e] = __ldg(&msg4[(e0 + e) * (D / 4) + lane]);

#pragma unroll
            for (int e = 0; e < 4; e++) {
                if (e >= nb) break;
                int seg = __shfl_sync(0xffffffffu, seg_l, e);
                float* dst = out + (long long)seg * D + lane * 4;
                asm volatile("red.global.add.v4.f32 [%0], {%1,%2,%3,%4};"
                             :: "l"(dst), "f"(v[e].x), "f"(v[e].y),
                                "f"(v[e].z), "f"(v[e].w) : "memory");
                if (lane == e)
                    atomicAdd(&g_counts[seg], 1);
            }
        }
    } else {
        // ---------------- TMA bulk-reduce path: edges [E_red, E) ----------------
        long long blk = (long long)g * 3 + (r - 4);
        long long wbase = E_red + blk * EPB + (long long)warp * 32;
        if (wbase >= E) return;

        int cur = 0;
#pragma unroll
        for (int b = 0; b < 8; b++) {
            long long e0 = wbase + b * TEB;
            if (e0 >= E) break;
            int nb = (int)min((long long)TEB, E - e0);

            int seg = (lane < nb) ? __ldg(&index[e0 + lane]) : 0;

#pragma unroll
            for (int e = 0; e < TEB; e++) {
                if (e >= nb) break;
                float4 v = __ldg(&msg4[(e0 + e) * (D / 4) + lane]);
                sbuf[warp][cur][e][lane] = v;
            }
            __syncwarp();

            if (lane < nb) {
                asm volatile("fence.proxy.async.shared::cta;" ::: "memory");
                uint32_t src = (uint32_t)__cvta_generic_to_shared(
                                   &sbuf[warp][cur][lane][0]);
                float* dst = out + (long long)seg * D;
                asm volatile(
                    "cp.reduce.async.bulk.global.shared::cta.bulk_group.add.f32 "
                    "[%0], [%1], %2;"
                    :: "l"(dst), "r"(src), "n"(D * 4) : "memory");
                asm volatile("cp.async.bulk.commit_group;" ::: "memory");
                atomicAdd(&g_counts[seg], 1);
            }

            cur ^= 1;
            if (lane < TEB)
                asm volatile("cp.async.bulk.wait_group 1;" ::: "memory");
            __syncwarp();
        }
        if (lane < TEB)
            asm volatile("cp.async.bulk.wait_group 0;" ::: "memory");
    }
}

// ---------------------------------------------------------------------------
// K2: divide sums by max(count, 1)
// ---------------------------------------------------------------------------
__global__ void divide_kernel(float4* __restrict__ out4, int N) {
    long long i = (long long)blockIdx.x * blockDim.x + threadIdx.x;
    long long total = (long long)N * (D / 4);
    if (i >= total) return;
    int row = (int)(i >> 5);           // D/4 == 32
    float c = (float)g_counts[row];
    float inv = 1.0f / fmaxf(c, 1.0f);
    float4 v = out4[i];
    v.x *= inv; v.y *= inv; v.z *= inv; v.w *= inv;
    out4[i] = v;
}

// ---------------------------------------------------------------------------
extern "C" void kernel_launch(void* const* d_in, const int* in_sizes, int n_in,
                              void* d_out, int out_size) {
    const float4* msg4  = (const float4*)d_in[0];
    const int*    index = (const int*)d_in[1];
    // d_in[2] (t) unused by the reference
    float* out = (float*)d_out;

    long long E = in_sizes[1];
    int N = out_size / D;
    long long n4 = (long long)out_size / 4;

    zero_kernel<<<2048, 256>>>((float4*)out, n4, N);

    // split: 4/7 of edges to REDG, 3/7 to TMA (matches measured pipe rates)
    long long E_red = E * 4 / 7;
    long long blocks_red = (E_red + EPB - 1) / EPB;
    long long blocks_tma = (E - E_red + EPB - 1) / EPB;
    long long groups = max((blocks_red + 3) / 4, (blocks_tma + 2) / 3);
    int grid = (int)(groups * 7);

    hybrid_kernel<<<grid, 256>>>(msg4, index, out, E_red, E);

    {
        long long total = (long long)N * (D / 4);
        int blocks = (int)((total + 255) / 256);
        divide_kernel<<<blocks, 256>>>((float4*)out, N);
    }
}